// round 3
// baseline (speedup 1.0000x reference)
#include <cuda_runtime.h>
#include <cuda_bf16.h>
#include <math.h>

// Problem constants
#define B     256
#define V     100
#define C     40
#define E     128
#define H     100
#define G4    400      // 4*H
#define M_TOT 32768    // B*E

typedef unsigned long long u64;

// ---------------- device scratch ----------------
__device__ int   g_is64;
__device__ int   g_last[B];
__device__ float g_xseq[B * V * E];        // sum_embed flat == A[32768][100]
__device__ float g_xpart[M_TOT * G4];      // x @ W_ih^T + b_ih + b_hh
__device__ float g_trueh[B * E];

// packed fp32x2 FMA: d.lo += a.lo*b.lo, d.hi += a.hi*b.hi  (exact fp32)
__device__ __forceinline__ void ffma2(u64& d, u64 a, u64 b) {
    asm("fma.rn.f32x2 %0, %1, %2, %0;" : "+l"(d) : "l"(a), "l"(b));
}
__device__ __forceinline__ u64 pack2(float lo, float hi) {
    u64 r; asm("mov.b64 %0, {%1, %2};" : "=l"(r) : "f"(lo), "f"(hi)); return r;
}
__device__ __forceinline__ void unpack2(u64 v, float& lo, float& hi) {
    asm("mov.b64 {%0, %1}, %2;" : "=f"(lo), "=f"(hi) : "l"(v));
}

// ---------------- K-1: detect int32 vs int64 diag_x ----------------
__global__ void k_detect(const int* __restrict__ p) {
    int v = p[2 * threadIdx.x + 1];
    int any = __syncthreads_or(v != 0);
    if (threadIdx.x == 0) g_is64 = any ? 0 : 1;
}

// ---------------- K0: last visit index per batch row ----------------
__global__ void k_last(const float* __restrict__ mask) {
    __shared__ int red[128];
    int b = blockIdx.x, tid = threadIdx.x;
    int best = -1;
    if (tid < V) {
        const float* mp = mask + (b * V + tid) * C;
        bool has = false;
        #pragma unroll 8
        for (int c = 0; c < C; c++) has |= (mp[c] != 0.f);
        if (has) best = tid;
    }
    red[tid] = best;
    __syncthreads();
    #pragma unroll
    for (int s = 64; s > 0; s >>= 1) {
        if (tid < s) red[tid] = max(red[tid], red[tid + s]);
        __syncthreads();
    }
    if (tid == 0) g_last[b] = (red[0] < 0) ? (V - 1) : red[0];
}

// ---------------- K1: masked embedding sum ----------------
__global__ void k_embed(const int* __restrict__ diag,
                        const float* __restrict__ mask,
                        const float* __restrict__ table) {
    int is64 = g_is64;
    int p    = blockIdx.x * 8 + (threadIdx.x >> 5);
    int lane = threadIdx.x & 31;
    const float4* tab4 = (const float4*)table;
    float4 acc = make_float4(0.f, 0.f, 0.f, 0.f);
    int base = p * C;
    #pragma unroll 4
    for (int c = 0; c < C; c++) {
        int idx = base + c;
        float m = mask[idx];
        int code = diag[idx << is64];
        if (m != 0.f) {
            float4 t = tab4[code * 32 + lane];
            acc.x += t.x * m; acc.y += t.y * m; acc.z += t.z * m; acc.w += t.w * m;
        }
    }
    ((float4*)g_xseq)[p * 32 + lane] = acc;
}

// ---------------- K2: x_part = A @ W_ih^T + (b_ih + b_hh) ----------------
// A[32768,100], W[400,100]. BM=128, BN=80, KC=25 (4 chunks), 256 threads.
// Micro-tile: 8 m-rows (4 f32x2 pairs) x 5 n. B duplicated in smem as (b,b)
// pairs so every FFMA2 operand is a direct LDS.64/LDS.128 — no pack movs.
#define BM 128
#define BN 80
#define KC 25
#define ASTR 132   // floats per k-row (mult of 4 -> aligned u64 pairs)

__global__ void __launch_bounds__(256, 3) k_gemm(const float* __restrict__ W,
                                                 const float* __restrict__ bih,
                                                 const float* __restrict__ bhh) {
    __shared__ __align__(16) float  As[KC * ASTR];   // 13.2KB, [k][m]
    __shared__ __align__(8)  float2 Bs[KC * BN];     // 16KB,  [k][n] = (b,b)
    int tid = threadIdx.x;
    int m0 = blockIdx.x * BM;
    int n0 = blockIdx.y * BN;
    int tm = tid & 15;          // m group: rows tm*4..+3 and tm*4+64..+67
    int tg = tid >> 4;          // n group: cols tg*5..+4
    int tn0 = n0 + tg * 5;

    u64 acc[4][5];
    #pragma unroll
    for (int j = 0; j < 5; j++) {
        float bv = bih[tn0 + j] + bhh[tn0 + j];
        u64 pb = pack2(bv, bv);
        #pragma unroll
        for (int i = 0; i < 4; i++) acc[i][j] = pb;
    }

    #pragma unroll 1
    for (int kk = 0; kk < 4; kk++) {
        #pragma unroll
        for (int i = 0; i < 13; i++) {
            int li = tid + i * 256;
            if (li < BM * KC) {
                int m = li / KC, k = li % KC;
                As[k * ASTR + m] = g_xseq[(m0 + m) * 100 + kk * KC + k];
            }
        }
        #pragma unroll
        for (int i = 0; i < 8; i++) {
            int li = tid + i * 256;
            if (li < BN * KC) {
                int n = li / KC, k = li % KC;
                float v = W[(n0 + n) * 100 + kk * KC + k];
                Bs[k * BN + n] = make_float2(v, v);
            }
        }
        __syncthreads();

        #pragma unroll 5
        for (int k = 0; k < KC; k++) {
            const u64* ap = (const u64*)(As + k * ASTR);
            u64 a[4];
            a[0] = ap[tm * 2];       a[1] = ap[tm * 2 + 1];
            a[2] = ap[tm * 2 + 32];  a[3] = ap[tm * 2 + 33];
            const u64* bp = (const u64*)(Bs + k * BN + tg * 5);
            #pragma unroll
            for (int j = 0; j < 5; j++) {
                u64 bv = bp[j];
                #pragma unroll
                for (int i = 0; i < 4; i++) ffma2(acc[i][j], a[i], bv);
            }
        }
        __syncthreads();
    }

    #pragma unroll
    for (int i = 0; i < 4; i++) {
        int r = m0 + ((i < 2) ? (tm * 4 + 2 * i) : (tm * 4 + 64 + 2 * (i - 2)));
        #pragma unroll
        for (int j = 0; j < 5; j++) {
            float lo, hi;
            unpack2(acc[i][j], lo, hi);
            g_xpart[r * G4 + tn0 + j]       = lo;
            g_xpart[(r + 1) * G4 + tn0 + j] = hi;
        }
    }
}

// ---------------- K3: recurrent LSTM, one CTA per embed-row ----------------
// 800 thr = 2 per gate (k-split 50/50), W_hh rows as 26 f32x2 register pairs.
// h broadcast-read as ulonglong2 (LDS.128); x_part prefetched one step ahead.
__device__ __forceinline__ float sigf(float x) {
    return 1.f / (1.f + __expf(-x));
}
__device__ __forceinline__ float tanhfast(float x) {
    x = fminf(fmaxf(x, -15.f), 15.f);
    float e = __expf(2.f * x);
    return (e - 1.f) / (e + 1.f);
}

__global__ void __launch_bounds__(800, 1) k_rec(const float* __restrict__ Whh) {
    __shared__ __align__(16) float h_a[52];   // h[0..49] + zero pad
    __shared__ __align__(16) float h_b[52];   // h[50..99] + zero pad
    __shared__ float gates_s[G4];
    __shared__ int   last_s[B];

    int tid  = threadIdx.x;
    int e    = blockIdx.x;
    int g    = tid >> 1;
    int half = tid & 1;

    // weight pairs in registers (row 8B-aligned: g*400B + half*200B)
    u64 wp[26];
    const u64* wsrc = (const u64*)(Whh + g * 100 + half * 50);
    #pragma unroll
    for (int j = 0; j < 25; j++) wp[j] = wsrc[j];
    wp[25] = 0ULL;                           // covers zero pad h[50..51]

    for (int i = tid; i < B; i += 800) last_s[i] = g_last[i];
    if (tid < 52) { h_a[tid] = 0.f; h_b[tid] = 0.f; }
    float c = 0.f;
    __syncthreads();

    const float* xp = g_xpart + e * G4 + g;      // step stride E*G4
    float* th = g_trueh + e;
    const ulonglong2* hv2 = half ? (const ulonglong2*)h_b : (const ulonglong2*)h_a;

    float xv_next = (!half) ? __ldg(xp) : 0.f;   // prefetch t=0

    #pragma unroll 1
    for (int t = 0; t < B; t++) {
        float xv = xv_next;
        if (!half && t + 1 < B) xv_next = __ldg(xp + (t + 1) * (E * G4));

        u64 acc0 = 0ULL, acc1 = 0ULL;            // (0.f,0.f)
        #pragma unroll
        for (int j = 0; j < 13; j++) {
            ulonglong2 hv = hv2[j];
            ffma2(acc0, wp[2 * j],     hv.x);
            ffma2(acc1, wp[2 * j + 1], hv.y);
        }
        float a0, a1, a2, a3;
        unpack2(acc0, a0, a1);
        unpack2(acc1, a2, a3);
        float acc = (a0 + a2) + (a1 + a3);
        acc += __shfl_down_sync(0xFFFFFFFFu, acc, 1);

        if (!half) {
            float pre = acc + xv;
            float a = (g < 200 || g >= 300) ? sigf(pre) : tanhfast(pre);
            gates_s[g] = a;
        }
        __syncthreads();

        if (tid < H) {
            float iv = gates_s[tid];
            float fv = gates_s[H + tid];
            float gv = gates_s[2 * H + tid];
            float ov = gates_s[3 * H + tid];
            c = fv * c + iv * gv;
            float hval = ov * tanhfast(c);
            if (tid < 50) h_a[tid] = hval; else h_b[tid - 50] = hval;
            if (tid == last_s[t]) th[t * E] = hval;
        }
        __syncthreads();
    }
}

// ---------------- K4: final FC + sigmoid ----------------
__global__ void k_fc(const float* __restrict__ fcw,
                     const float* __restrict__ fcb,
                     float* __restrict__ out) {
    int warp = (blockIdx.x * blockDim.x + threadIdx.x) >> 5;
    int lane = threadIdx.x & 31;
    if (warp >= B) return;
    const float* th = g_trueh + warp * E;
    float acc = 0.f;
    #pragma unroll
    for (int k = 0; k < 4; k++) acc += th[lane + 32 * k] * fcw[lane + 32 * k];
    #pragma unroll
    for (int s = 16; s > 0; s >>= 1) acc += __shfl_down_sync(0xFFFFFFFFu, acc, s);
    if (lane == 0) out[warp] = 1.f / (1.f + __expf(-(acc + fcb[0])));
}

// ---------------- launcher: kernel launches ONLY ----------------
extern "C" void kernel_launch(void* const* d_in, const int* in_sizes, int n_in,
                              void* d_out, int out_size) {
    const int*   diag = (const int*)d_in[0];
    const float* mask = (const float*)d_in[1];
    const float* tab  = (const float*)d_in[2];
    const float* Wih  = (const float*)d_in[3];
    const float* Whh  = (const float*)d_in[4];
    const float* bih  = (const float*)d_in[5];
    const float* bhh  = (const float*)d_in[6];
    const float* fcw  = (const float*)d_in[7];
    const float* fcb  = (const float*)d_in[8];
    float* out = (float*)d_out;

    (void)in_sizes; (void)n_in; (void)out_size;

    k_detect<<<1, 256>>>(diag);
    k_last<<<B, 128>>>(mask);
    k_embed<<<(B * V) / 8, 256>>>(diag, mask, tab);
    k_gemm<<<dim3(M_TOT / BM, G4 / BN), 256>>>(Wih, bih, bhh);
    k_rec<<<E, 800>>>(Whh);
    k_fc<<<32, 256>>>(fcw, fcb, out);
}

// round 4
// speedup vs baseline: 1.0202x; 1.0202x over previous
#include <cuda_runtime.h>
#include <cuda_bf16.h>
#include <math.h>

// Problem constants
#define B     256
#define V     100
#define C     40
#define E     128
#define H     100
#define G4    400      // 4*H
#define M_TOT 32768    // B*E

// ---------------- device scratch ----------------
__device__ int   g_is64;
__device__ int   g_last[B];
__device__ float g_xseq[B * V * E];        // sum_embed flat == A[32768][100]
__device__ float g_xpart[M_TOT * G4];      // x @ W_ih^T + b_ih + b_hh
__device__ float g_trueh[B * E];

// ---------------- K-1: detect int32 vs int64 diag_x ----------------
__global__ void k_detect(const int* __restrict__ p) {
    int v = p[2 * threadIdx.x + 1];
    int any = __syncthreads_or(v != 0);
    if (threadIdx.x == 0) g_is64 = any ? 0 : 1;
}

// ---------------- K0: last visit index per batch row ----------------
__global__ void k_last(const float* __restrict__ mask) {
    __shared__ int red[128];
    int b = blockIdx.x, tid = threadIdx.x;
    int best = -1;
    if (tid < V) {
        const float* mp = mask + (b * V + tid) * C;
        bool has = false;
        #pragma unroll 8
        for (int c = 0; c < C; c++) has |= (mp[c] != 0.f);
        if (has) best = tid;
    }
    red[tid] = best;
    __syncthreads();
    #pragma unroll
    for (int s = 64; s > 0; s >>= 1) {
        if (tid < s) red[tid] = max(red[tid], red[tid + s]);
        __syncthreads();
    }
    if (tid == 0) g_last[b] = (red[0] < 0) ? (V - 1) : red[0];
}

// ---------------- K1: masked embedding sum ----------------
// One warp per (b,v); lane holds 4 of 128 embed dims as float4.
__global__ void k_embed(const int* __restrict__ diag,
                        const float* __restrict__ mask,
                        const float* __restrict__ table) {
    int is64 = g_is64;
    int p    = blockIdx.x * 8 + (threadIdx.x >> 5);
    int lane = threadIdx.x & 31;
    const float4* tab4 = (const float4*)table;
    float4 acc = make_float4(0.f, 0.f, 0.f, 0.f);
    int base = p * C;
    #pragma unroll 4
    for (int c = 0; c < C; c++) {
        int idx = base + c;
        float m = mask[idx];
        int code = diag[idx << is64];
        if (m != 0.f) {
            float4 t = tab4[code * 32 + lane];
            acc.x += t.x * m; acc.y += t.y * m; acc.z += t.z * m; acc.w += t.w * m;
        }
    }
    ((float4*)g_xseq)[p * 32 + lane] = acc;
}

// ---------------- K2: x_part = A @ W_ih^T + (b_ih + b_hh) ----------------
// A[32768,100], W[400,100]. BM=128, BN=80, KC=25 (4 chunks), 256 threads.
// Micro-tile 8m x 5n; m rows CONTIGUOUS (tm*8..+7) so A reads are two
// LDS.128 per k (conflict-free). B scalars broadcast. 3 CTAs/SM target.
#define BM 128
#define BN 80
#define KC 25
#define ASTR 132   // pad to mult of 4, conflict-free float4 reads
#define BSTR 81

__global__ void __launch_bounds__(256, 3) k_gemm(const float* __restrict__ W,
                                                 const float* __restrict__ bih,
                                                 const float* __restrict__ bhh) {
    __shared__ __align__(16) float As[KC * ASTR];   // 13.2KB, [k][m]
    __shared__ float Bs[KC * BSTR];                 //  8.1KB, [k][n]
    int tid = threadIdx.x;
    int m0 = blockIdx.x * BM;
    int n0 = blockIdx.y * BN;
    int tm = tid & 15;          // m rows tm*8 .. tm*8+7
    int tg = tid >> 4;          // n cols tg*5 .. tg*5+4
    int tn0 = n0 + tg * 5;

    float acc[8][5];
    #pragma unroll
    for (int j = 0; j < 5; j++) {
        float bv = bih[tn0 + j] + bhh[tn0 + j];
        #pragma unroll
        for (int i = 0; i < 8; i++) acc[i][j] = bv;
    }

    #pragma unroll 1
    for (int kk = 0; kk < 4; kk++) {
        // A chunk: BM*KC = 3200 elems (13 iters); consecutive tids read
        // 25-float contiguous gmem runs, store k-major
        #pragma unroll
        for (int i = 0; i < 13; i++) {
            int li = tid + i * 256;
            if (li < BM * KC) {
                int m = li / KC, k = li % KC;
                As[k * ASTR + m] = g_xseq[(m0 + m) * 100 + kk * KC + k];
            }
        }
        // B chunk: BN*KC = 2000 elems (8 iters)
        #pragma unroll
        for (int i = 0; i < 8; i++) {
            int li = tid + i * 256;
            if (li < BN * KC) {
                int n = li / KC, k = li % KC;
                Bs[k * BSTR + n] = W[(n0 + n) * 100 + kk * KC + k];
            }
        }
        __syncthreads();

        #pragma unroll 5
        for (int k = 0; k < KC; k++) {
            const float4* ap = (const float4*)(As + k * ASTR + tm * 8);
            float4 a0 = ap[0];
            float4 a1 = ap[1];
            float a[8] = {a0.x, a0.y, a0.z, a0.w, a1.x, a1.y, a1.z, a1.w};
            float bb[5];
            #pragma unroll
            for (int j = 0; j < 5; j++) bb[j] = Bs[k * BSTR + tg * 5 + j];
            #pragma unroll
            for (int i = 0; i < 8; i++)
                #pragma unroll
                for (int j = 0; j < 5; j++) acc[i][j] += a[i] * bb[j];
        }
        __syncthreads();
    }

    #pragma unroll
    for (int i = 0; i < 8; i++) {
        int r = m0 + tm * 8 + i;
        #pragma unroll
        for (int j = 0; j < 5; j++)
            g_xpart[r * G4 + tn0 + j] = acc[i][j];
    }
}

// ---------------- K3: recurrent LSTM, one CTA per embed-row ----------------
// 800 thr = 2 per gate (k-split 50/50), W_hh rows in registers; h broadcast
// float4 LDS; x_part PREFETCHED one step ahead (hides DRAM/L2 latency).
__device__ __forceinline__ float sigf(float x) {
    return 1.f / (1.f + __expf(-x));
}
__device__ __forceinline__ float tanhfast(float x) {
    x = fminf(fmaxf(x, -15.f), 15.f);
    float e = __expf(2.f * x);
    return (e - 1.f) / (e + 1.f);
}

__global__ void __launch_bounds__(800, 1) k_rec(const float* __restrict__ Whh) {
    __shared__ __align__(16) float h_a[52];   // h[0..49] + zero pad
    __shared__ __align__(16) float h_b[52];   // h[50..99] + zero pad
    __shared__ float gates_s[G4];
    __shared__ int   last_s[B];

    int tid  = threadIdx.x;
    int e    = blockIdx.x;
    int g    = tid >> 1;
    int half = tid & 1;

    float w[52];
    #pragma unroll
    for (int j = 0; j < 50; j++) w[j] = Whh[g * 100 + half * 50 + j];
    w[50] = 0.f; w[51] = 0.f;

    for (int i = tid; i < B; i += 800) last_s[i] = g_last[i];
    if (tid < 52) { h_a[tid] = 0.f; h_b[tid] = 0.f; }
    float c = 0.f;
    __syncthreads();

    const float* xp = g_xpart + e * G4 + g;      // step stride = E*G4
    float* th = g_trueh + e;
    const float4* hv4 = half ? (const float4*)h_b : (const float4*)h_a;

    float xv_next = (!half) ? __ldg(xp) : 0.f;   // prefetch t=0

    #pragma unroll 1
    for (int t = 0; t < B; t++) {
        float xv = xv_next;
        if (!half && t + 1 < B) xv_next = __ldg(xp + (t + 1) * (E * G4));

        float ax = 0.f, ay = 0.f, az = 0.f, aw = 0.f;
        #pragma unroll
        for (int j = 0; j < 13; j++) {
            float4 hv = hv4[j];
            ax += w[4 * j + 0] * hv.x;
            ay += w[4 * j + 1] * hv.y;
            az += w[4 * j + 2] * hv.z;
            aw += w[4 * j + 3] * hv.w;
        }
        float acc = (ax + ay) + (az + aw);
        acc += __shfl_down_sync(0xFFFFFFFFu, acc, 1);

        if (!half) {
            float pre = acc + xv;
            float a = (g < 200 || g >= 300) ? sigf(pre) : tanhfast(pre);
            gates_s[g] = a;
        }
        __syncthreads();

        if (tid < H) {
            float iv = gates_s[tid];
            float fv = gates_s[H + tid];
            float gv = gates_s[2 * H + tid];
            float ov = gates_s[3 * H + tid];
            c = fv * c + iv * gv;
            float hval = ov * tanhfast(c);
            if (tid < 50) h_a[tid] = hval; else h_b[tid - 50] = hval;
            if (tid == last_s[t]) th[t * E] = hval;
        }
        __syncthreads();
    }
}

// ---------------- K4: final FC + sigmoid ----------------
__global__ void k_fc(const float* __restrict__ fcw,
                     const float* __restrict__ fcb,
                     float* __restrict__ out) {
    int warp = (blockIdx.x * blockDim.x + threadIdx.x) >> 5;
    int lane = threadIdx.x & 31;
    if (warp >= B) return;
    const float* th = g_trueh + warp * E;
    float acc = 0.f;
    #pragma unroll
    for (int k = 0; k < 4; k++) acc += th[lane + 32 * k] * fcw[lane + 32 * k];
    #pragma unroll
    for (int s = 16; s > 0; s >>= 1) acc += __shfl_down_sync(0xFFFFFFFFu, acc, s);
    if (lane == 0) out[warp] = 1.f / (1.f + __expf(-(acc + fcb[0])));
}

// ---------------- launcher: kernel launches ONLY ----------------
extern "C" void kernel_launch(void* const* d_in, const int* in_sizes, int n_in,
                              void* d_out, int out_size) {
    const int*   diag = (const int*)d_in[0];
    const float* mask = (const float*)d_in[1];
    const float* tab  = (const float*)d_in[2];
    const float* Wih  = (const float*)d_in[3];
    const float* Whh  = (const float*)d_in[4];
    const float* bih  = (const float*)d_in[5];
    const float* bhh  = (const float*)d_in[6];
    const float* fcw  = (const float*)d_in[7];
    const float* fcb  = (const float*)d_in[8];
    float* out = (float*)d_out;

    (void)in_sizes; (void)n_in; (void)out_size;

    k_detect<<<1, 256>>>(diag);
    k_last<<<B, 128>>>(mask);
    k_embed<<<(B * V) / 8, 256>>>(diag, mask, tab);
    k_gemm<<<dim3(M_TOT / BM, G4 / BN), 256>>>(Wih, bih, bhh);
    k_rec<<<E, 800>>>(Whh);
    k_fc<<<32, 256>>>(fcw, fcb, out);
}

// round 6
// speedup vs baseline: 2.0081x; 1.9684x over previous
#include <cuda_runtime.h>
#include <cuda_fp16.h>
#include <cuda_bf16.h>
#include <math.h>

// Problem constants
#define B     256
#define V     100
#define C     40
#define E     128
#define H     100
#define G4    400      // 4*H
#define M_TOT 32768    // B*E

// ---------------- device scratch ----------------
__device__ int   g_last[B];
__device__ __align__(16) float g_xseq[B * V * E];    // A[32768][100]
__device__ __align__(16) float g_xpart[M_TOT * G4];  // x @ W_ih^T + biases
__device__ float g_trueh[B * E];

// ---------------- tf32 helpers ----------------
__device__ __forceinline__ unsigned f2tf32(float f) {
    unsigned r;
    asm("cvt.rna.tf32.f32 %0, %1;" : "=r"(r) : "f"(f));
    return r;
}
__device__ __forceinline__ void split_tf32(float a, unsigned& hi, unsigned& lo) {
    hi = f2tf32(a);
    lo = f2tf32(a - __uint_as_float(hi));
}
__device__ __forceinline__ void mma8(float* d, const unsigned* a,
                                     unsigned b0, unsigned b1) {
    asm("mma.sync.aligned.m16n8k8.row.col.f32.tf32.tf32.f32 "
        "{%0,%1,%2,%3},{%4,%5,%6,%7},{%8,%9},{%0,%1,%2,%3};"
        : "+f"(d[0]), "+f"(d[1]), "+f"(d[2]), "+f"(d[3])
        : "r"(a[0]), "r"(a[1]), "r"(a[2]), "r"(a[3]), "r"(b0), "r"(b1));
}

// ---------------- K0: last visit index per batch row ----------------
__global__ void k_last(const float* __restrict__ mask) {
    __shared__ int red[128];
    int b = blockIdx.x, tid = threadIdx.x;
    int best = -1;
    if (tid < V) {
        const float* mp = mask + (b * V + tid) * C;
        bool has = false;
        #pragma unroll 8
        for (int c = 0; c < C; c++) has |= (mp[c] != 0.f);
        if (has) best = tid;
    }
    red[tid] = best;
    __syncthreads();
    #pragma unroll
    for (int s = 64; s > 0; s >>= 1) {
        if (tid < s) red[tid] = max(red[tid], red[tid + s]);
        __syncthreads();
    }
    if (tid == 0) g_last[b] = (red[0] < 0) ? (V - 1) : red[0];
}

// ---------------- K1: masked embedding sum (+inline dtype detect) ----------
__global__ void k_embed(const int* __restrict__ diag,
                        const float* __restrict__ mask,
                        const float* __restrict__ table) {
    // per-block int64 probe: odd 32-bit words all zero <=> int64
    int flag = 0;
    if (threadIdx.x < 64) flag = diag[2 * threadIdx.x + 1];
    int is64 = __syncthreads_or(flag != 0) ? 0 : 1;

    int p    = blockIdx.x * 8 + (threadIdx.x >> 5);   // (b*V + v)
    int lane = threadIdx.x & 31;
    const float4* tab4 = (const float4*)table;
    float4 acc = make_float4(0.f, 0.f, 0.f, 0.f);
    int base = p * C;
    #pragma unroll 4
    for (int c = 0; c < C; c++) {
        int idx = base + c;
        float m = mask[idx];
        int code = diag[idx << is64];
        if (m != 0.f) {
            float4 t = tab4[code * 32 + lane];
            acc.x += t.x * m; acc.y += t.y * m; acc.z += t.z * m; acc.w += t.w * m;
        }
    }
    ((float4*)g_xseq)[p * 32 + lane] = acc;
}

// ---------------- K2: 3xTF32 tensor GEMM ----------------
// x_part[32768,400] = A[32768,100] @ W[400,100]^T + (b_ih + b_hh)
// CTA 256 thr (8 warps 4m x 2n), tile 128m x 80n, K chunks of 32.
#define BMg 128
#define BNg 80
#define SST 36    // smem k-stride (conflict-free fragment reads)

__global__ void __launch_bounds__(256, 2) k_gemm(const float* __restrict__ W,
                                                 const float* __restrict__ bih,
                                                 const float* __restrict__ bhh) {
    __shared__ float    As[BMg * SST];   // fp32 A tile [m][k]   18.4KB
    __shared__ unsigned Wh[BNg * SST];   // tf32-hi W   [n][k]   11.5KB
    __shared__ unsigned Wl[BNg * SST];   // tf32-lo W   [n][k]   11.5KB

    int tid = threadIdx.x;
    int wid = tid >> 5, lane = tid & 31;
    int wm = wid & 3, wn = wid >> 2;     // warp grid 4m x 2n
    int g = lane >> 2, t = lane & 3;     // mma lane coords
    int m0 = blockIdx.x * BMg;
    int n0 = blockIdx.y * BNg;

    float d[2][5][4];
    #pragma unroll
    for (int ni = 0; ni < 5; ni++) {
        int cc = n0 + wn * 40 + ni * 8 + 2 * t;
        float b0 = bih[cc] + bhh[cc];
        float b1 = bih[cc + 1] + bhh[cc + 1];
        #pragma unroll
        for (int mi = 0; mi < 2; mi++) {
            d[mi][ni][0] = b0; d[mi][ni][1] = b1;
            d[mi][ni][2] = b0; d[mi][ni][3] = b1;
        }
    }

    #pragma unroll 1
    for (int kc = 0; kc < 4; kc++) {
        int k0 = kc * 32;
        #pragma unroll
        for (int i = 0; i < 16; i++) {
            int li = i * 256 + tid;
            int m = li >> 5, k = li & 31;
            As[m * SST + k] = (k0 + k < 100) ? g_xseq[(m0 + m) * 100 + k0 + k] : 0.f;
        }
        #pragma unroll
        for (int i = 0; i < 10; i++) {
            int li = i * 256 + tid;
            int n = li >> 5, k = li & 31;
            float w = (k0 + k < 100) ? W[(n0 + n) * 100 + k0 + k] : 0.f;
            unsigned hi, lo;
            split_tf32(w, hi, lo);
            Wh[n * SST + k] = hi;
            Wl[n * SST + k] = lo;
        }
        __syncthreads();

        int ns = (kc == 3) ? 1 : 4;      // last chunk covers k 96..99 only
        #pragma unroll
        for (int s = 0; s < 4; s++) {
            if (s >= ns) break;
            unsigned ah[2][4], al[2][4];
            #pragma unroll
            for (int mi = 0; mi < 2; mi++) {
                int r = (wm * 32 + mi * 16 + g) * SST + s * 8 + t;
                split_tf32(As[r],               ah[mi][0], al[mi][0]);
                split_tf32(As[r + 8 * SST],     ah[mi][1], al[mi][1]);
                split_tf32(As[r + 4],           ah[mi][2], al[mi][2]);
                split_tf32(As[r + 8 * SST + 4], ah[mi][3], al[mi][3]);
            }
            #pragma unroll
            for (int ni = 0; ni < 5; ni++) {
                int rb = (wn * 40 + ni * 8 + g) * SST + s * 8 + t;
                unsigned bh0 = Wh[rb], bh1 = Wh[rb + 4];
                unsigned bl0 = Wl[rb], bl1 = Wl[rb + 4];
                #pragma unroll
                for (int mi = 0; mi < 2; mi++) {
                    mma8(d[mi][ni], ah[mi], bh0, bh1);   // hi*hi
                    mma8(d[mi][ni], ah[mi], bl0, bl1);   // hi*lo
                    mma8(d[mi][ni], al[mi], bh0, bh1);   // lo*hi
                }
            }
        }
        __syncthreads();
    }

    #pragma unroll
    for (int mi = 0; mi < 2; mi++) {
        int r = m0 + wm * 32 + mi * 16 + g;
        #pragma unroll
        for (int ni = 0; ni < 5; ni++) {
            int cc = n0 + wn * 40 + ni * 8 + 2 * t;
            *(float2*)&g_xpart[r * G4 + cc]       = make_float2(d[mi][ni][0], d[mi][ni][1]);
            *(float2*)&g_xpart[(r + 8) * G4 + cc] = make_float2(d[mi][ni][2], d[mi][ni][3]);
        }
    }
}

// ---------------- K3: fp16 HFMA2 recurrence, one CTA per embed-row --------
// 416 thr, 1 thread per gate (g<400). W_hh row as 52 half2 regs; h as fp16
// in smem read via LDS.128. x_part prefetch pointer CLAMPED to gate 399
// (threads 400..415 redundantly read gate 399 -> always in bounds).
__device__ __forceinline__ float sigf(float x) {
    return 1.f / (1.f + __expf(-x));
}
__device__ __forceinline__ float tanhfast(float x) {
    x = fminf(fmaxf(x, -15.f), 15.f);
    float e = __expf(2.f * x);
    return (e - 1.f) / (e + 1.f);
}

__global__ void __launch_bounds__(416, 1) k_rec(const float* __restrict__ Whh) {
    __shared__ __align__(16) __half h_h[104];   // h[0..99] + zero pad
    __shared__ float gates_s[G4];
    __shared__ int   last_s[B];

    int tid = threadIdx.x;
    int e   = blockIdx.x;
    int g   = tid;            // gate index (valid < 400)
    int gc  = (g < G4) ? g : (G4 - 1);   // clamped for safe gmem addressing

    // 52 half2 weight regs (pads zero)
    __half2 w2[52];
    #pragma unroll
    for (int j = 0; j < 50; j++) {
        float lo = 0.f, hi = 0.f;
        if (g < G4) {
            lo = Whh[g * 100 + 2 * j];
            hi = Whh[g * 100 + 2 * j + 1];
        }
        w2[j] = __floats2half2_rn(lo, hi);
    }
    w2[50] = __floats2half2_rn(0.f, 0.f);
    w2[51] = __floats2half2_rn(0.f, 0.f);

    for (int i = tid; i < B; i += 416) last_s[i] = g_last[i];
    if (tid < 104) h_h[tid] = __float2half_rn(0.f);
    float c = 0.f;
    __syncthreads();

    const float* xp = g_xpart + e * G4 + gc;  // step stride = E*G4, in-bounds
    float* th = g_trueh + e;
    const float4* hvec = (const float4*)h_h;  // 13 x float4 = 104 halfs

    float xv_next = __ldg(xp);                // prefetch t=0 (branchless)

    #pragma unroll 1
    for (int t = 0; t < B; t++) {
        float xv = xv_next;
        int tn = (t + 1 < B) ? (t + 1) : (B - 1);
        xv_next = __ldg(xp + tn * (E * G4));  // branchless clamped prefetch

        __half2 a0 = __floats2half2_rn(0.f, 0.f), a1 = a0, a2 = a0, a3 = a0;
        #pragma unroll
        for (int j = 0; j < 13; j++) {
            float4 hv = hvec[j];
            __half2 p0 = *(__half2*)&hv.x;
            __half2 p1 = *(__half2*)&hv.y;
            __half2 p2 = *(__half2*)&hv.z;
            __half2 p3 = *(__half2*)&hv.w;
            a0 = __hfma2(w2[4 * j + 0], p0, a0);
            a1 = __hfma2(w2[4 * j + 1], p1, a1);
            a2 = __hfma2(w2[4 * j + 2], p2, a2);
            a3 = __hfma2(w2[4 * j + 3], p3, a3);
        }
        float2 f0 = __half22float2(a0);
        float2 f1 = __half22float2(a1);
        float2 f2 = __half22float2(a2);
        float2 f3 = __half22float2(a3);
        float dot = ((f0.x + f0.y) + (f1.x + f1.y)) +
                    ((f2.x + f2.y) + (f3.x + f3.y));

        if (g < G4) {
            float pre = dot + xv;
            float a = (g < 200 || g >= 300) ? sigf(pre) : tanhfast(pre);
            gates_s[g] = a;
        }
        __syncthreads();

        if (tid < H) {
            float iv = gates_s[tid];
            float fv = gates_s[H + tid];
            float gv = gates_s[2 * H + tid];
            float ov = gates_s[3 * H + tid];
            c = fv * c + iv * gv;
            float hval = ov * tanhfast(c);
            h_h[tid] = __float2half_rn(hval);
            if (tid == last_s[t]) th[t * E] = hval;
        }
        __syncthreads();
    }
}

// ---------------- K4: final FC + sigmoid ----------------
__global__ void k_fc(const float* __restrict__ fcw,
                     const float* __restrict__ fcb,
                     float* __restrict__ out) {
    int warp = (blockIdx.x * blockDim.x + threadIdx.x) >> 5;
    int lane = threadIdx.x & 31;
    if (warp >= B) return;
    const float* th = g_trueh + warp * E;
    float acc = 0.f;
    #pragma unroll
    for (int k = 0; k < 4; k++) acc += th[lane + 32 * k] * fcw[lane + 32 * k];
    #pragma unroll
    for (int s = 16; s > 0; s >>= 1) acc += __shfl_down_sync(0xFFFFFFFFu, acc, s);
    if (lane == 0) out[warp] = 1.f / (1.f + __expf(-(acc + fcb[0])));
}

// ---------------- launcher: kernel launches ONLY ----------------
extern "C" void kernel_launch(void* const* d_in, const int* in_sizes, int n_in,
                              void* d_out, int out_size) {
    const int*   diag = (const int*)d_in[0];
    const float* mask = (const float*)d_in[1];
    const float* tab  = (const float*)d_in[2];
    const float* Wih  = (const float*)d_in[3];
    const float* Whh  = (const float*)d_in[4];
    const float* bih  = (const float*)d_in[5];
    const float* bhh  = (const float*)d_in[6];
    const float* fcw  = (const float*)d_in[7];
    const float* fcb  = (const float*)d_in[8];
    float* out = (float*)d_out;

    (void)in_sizes; (void)n_in; (void)out_size;

    k_last<<<B, 128>>>(mask);
    k_embed<<<(B * V) / 8, 256>>>(diag, mask, tab);
    k_gemm<<<dim3(M_TOT / BMg, G4 / BNg), 256>>>(Wih, bih, bhh);
    k_rec<<<E, 416>>>(Whh);
    k_fc<<<32, 256>>>(fcw, fcb, out);
}